// round 6
// baseline (speedup 1.0000x reference)
#include <cuda_runtime.h>

// SubGraphAvgPool: out[b,g,d] = mean(h[b,g,d], h[b,4g+1..4g+4,d]),  B=16, N=8193, D=512, G=2048.
//
// Persistent grid-stride kernel, FULL occupancy: 2432 CTAs (16/SM, 64 warps/SM)
// x 128 threads; each CTA loops over ~13.5 (b,g) units. Per iteration: 5
// independent LDG.128 per thread + 1 STG.128. Loop keeps DRAM queues fed with
// no wave-transition ramps; full warp complement maximizes SM-wide MLP.
//
// Cache hints (R2 winning policy):
//   - child rows >= 2049 (g >= 512): __ldcs  (single-use stream)
//   - child rows 1..2048:            default (re-read later as g-rows)
//   - g-node row:                    __ldcs  (last use, L2 hit)
//   - output:                        __stcs  (never re-read)

static constexpr int B = 16;
static constexpr long long N = 8193;
static constexpr int D = 512;
static constexpr int G = 2048;
static constexpr int DV = D / 4;        // 128 float4 per row
static constexpr int UNITS = B * G;     // 32768
static constexpr int GRID = 2432;       // 16 CTAs/SM on 152 SMs -> 64 warps/SM

__global__ __launch_bounds__(128, 16)
void subgraph_avgpool_kernel(const float* __restrict__ h, float* __restrict__ out) {
    const int dv = threadIdx.x;         // 0 .. 127
    const float4* __restrict__ hbase = reinterpret_cast<const float4*>(h) + dv;
    float4* __restrict__ obase = reinterpret_cast<float4*>(out) + dv;

    for (int u = blockIdx.x; u < UNITS; u += GRID) {
        const int g = u & (G - 1);      // G = 2048 = 2^11
        const int b = u >> 11;

        const float4* __restrict__ hp = hbase + (long long)b * (N * DV);

        // g-node row: last use (L2 hit from its earlier child-read)
        const float4 a0 = __ldcs(hp + (long long)g * DV);

        const float4* p = hp + (long long)(4 * g + 1) * DV;
        float4 a1, a2, a3, a4;
        if (g >= 512) {
            a1 = __ldcs(p);          a2 = __ldcs(p + DV);
            a3 = __ldcs(p + 2 * DV); a4 = __ldcs(p + 3 * DV);
        } else {
            a1 = __ldg(p);           a2 = __ldg(p + DV);
            a3 = __ldg(p + 2 * DV);  a4 = __ldg(p + 3 * DV);
        }

        float4 s;
        s.x = (a0.x + a1.x + a2.x + a3.x + a4.x) * 0.2f;
        s.y = (a0.y + a1.y + a2.y + a3.y + a4.y) * 0.2f;
        s.z = (a0.z + a1.z + a2.z + a3.z + a4.z) * 0.2f;
        s.w = (a0.w + a1.w + a2.w + a3.w + a4.w) * 0.2f;

        __stcs(obase + (long long)u * DV, s);
    }
}

extern "C" void kernel_launch(void* const* d_in, const int* in_sizes, int n_in,
                              void* d_out, int out_size) {
    const float* h = (const float*)d_in[0];
    float* out = (float*)d_out;
    subgraph_avgpool_kernel<<<GRID, 128>>>(h, out);
}

// round 7
// speedup vs baseline: 1.1084x; 1.1084x over previous
#include <cuda_runtime.h>

// SubGraphAvgPool: out[b,g,d] = mean(h[b,g,d], h[b,4g+1..4g+4,d]),  B=16, N=8193, D=512, G=2048.
//
// R2 winner structure (one CTA per (b,g), 128 threads, one float4 per thread),
// with load ordering tuned: the 4 contiguous DRAM-bound child loads issue
// FIRST (clean sequential burst, front of the L1tex wavefront queue), the
// (likely L2-hit) g-row load last.
//
// Cache hints:
//   - child rows >= 2049 (g >= 512): __ldcs  (single-use stream)
//   - child rows 1..2048:            default (re-read later as g-rows)
//   - g-node row:                    __ldcs  (last use)
//   - output:                        __stcs  (never re-read)

static constexpr int B = 16;
static constexpr long long N = 8193;
static constexpr int D = 512;
static constexpr int G = 2048;
static constexpr int DV = D / 4;  // 128 float4 per row

__global__ __launch_bounds__(128, 8)
void subgraph_avgpool_kernel(const float* __restrict__ h, float* __restrict__ out) {
    const int bg = blockIdx.x;          // 0 .. B*G-1
    const int g  = bg & (G - 1);        // G = 2048 = 2^11
    const int b  = bg >> 11;
    const int dv = threadIdx.x;         // 0 .. 127

    const float4* __restrict__ hp =
        reinterpret_cast<const float4*>(h) + (long long)b * (N * DV) + dv;

    // Child rows 4g+1..4g+4 first: the DRAM-bound contiguous burst.
    const float4* p = hp + (long long)(4 * g + 1) * DV;
    float4 a1, a2, a3, a4;
    if (g >= 512) {
        a1 = __ldcs(p);          a2 = __ldcs(p + DV);
        a3 = __ldcs(p + 2 * DV); a4 = __ldcs(p + 3 * DV);
    } else {
        a1 = __ldg(p);           a2 = __ldg(p + DV);
        a3 = __ldg(p + 2 * DV);  a4 = __ldg(p + 3 * DV);
    }

    // g-node row last: usually an L2 hit, cheap to hide.
    const float4 a0 = __ldcs(hp + (long long)g * DV);

    float4 s;
    s.x = (a0.x + a1.x + a2.x + a3.x + a4.x) * 0.2f;
    s.y = (a0.y + a1.y + a2.y + a3.y + a4.y) * 0.2f;
    s.z = (a0.z + a1.z + a2.z + a3.z + a4.z) * 0.2f;
    s.w = (a0.w + a1.w + a2.w + a3.w + a4.w) * 0.2f;

    __stcs(reinterpret_cast<float4*>(out) + (long long)bg * DV + dv, s);
}

extern "C" void kernel_launch(void* const* d_in, const int* in_sizes, int n_in,
                              void* d_out, int out_size) {
    const float* h = (const float*)d_in[0];
    float* out = (float*)d_out;
    subgraph_avgpool_kernel<<<B * G, 128>>>(h, out);
}